// round 14
// baseline (speedup 1.0000x reference)
#include <cuda_runtime.h>
#include <cuda_fp16.h>
#include <math.h>

#define N_NODES 50000
#define N_EDGES 800000
#define TOT_E   (N_EDGES + N_NODES)
#define IN_CH   128
#define HEADS   4
#define OUT_CH  64
#define HC      256
#define NEG_SLOPE 0.2f
#define SCAN_BLOCKS ((N_NODES + 1023) / 1024)   // 49
#define GB_TILE_M 32
#define GB_BLOCKS ((N_NODES + GB_TILE_M - 1) / GB_TILE_M)   // 1563
#define XS_LDH 136   // padded row stride in halves -> conflict-free frag loads

// ---- scratch (device globals; no allocation allowed) ----
__device__ __half g_xh [N_NODES * HC];      // projected features, fp16 (25.6MB, L2-resident)
__device__ float  g_asrc[N_NODES * HEADS];
__device__ float  g_adst[N_NODES * HEADS];
__device__ uint4  g_WtPh[8 * 16 * 32];      // B fragments fp16: [kt][ntp][lane]
__device__ int    g_deg [N_NODES];
__device__ int    g_rank[TOT_E];
__device__ int    g_incl[N_NODES];
__device__ int    g_bsum[SCAN_BLOCKS];
__device__ int    g_ptr [N_NODES + 1];      // CSR row ptr (by dst)
__device__ int    g_ssrc[TOT_E];            // dst-sorted: src node per slot
__device__ float  g_sexp[TOT_E * HEADS];    // dst-sorted: exp(alpha) per slot (fp32)

__device__ __forceinline__ float lrelu(float a) { return a > 0.f ? a : NEG_SLOPE * a; }

__device__ __forceinline__ unsigned h2u(__half2 h) {
    unsigned u; *(__half2*)&u = h; return u;
}
__device__ __forceinline__ void mma_f16(float* c,
                                        unsigned a0, unsigned a1, unsigned a2, unsigned a3,
                                        unsigned b0, unsigned b1) {
    asm("mma.sync.aligned.m16n8k16.row.col.f32.f16.f16.f32 "
        "{%0,%1,%2,%3}, {%4,%5,%6,%7}, {%8,%9}, {%0,%1,%2,%3};"
        : "+f"(c[0]), "+f"(c[1]), "+f"(c[2]), "+f"(c[3])
        : "r"(a0), "r"(a1), "r"(a2), "r"(a3), "r"(b0), "r"(b1));
}
__device__ __forceinline__ float sel_head(float4 e, int h) {
    return h == 0 ? e.x : (h == 1 ? e.y : (h == 2 ? e.z : e.w));
}
__device__ __forceinline__ void accum8(float* acc, uint4 r, float c) {
    const __half2* h = (const __half2*)&r;
    #pragma unroll
    for (int j = 0; j < 4; j++) {
        float2 f = __half22float2(h[j]);
        acc[2 * j]     += c * f.x;
        acc[2 * j + 1] += c * f.y;
    }
}

// ------- K0: zero deg + pack W into fp16 B-fragment layout -------
__global__ void k_prep(const float* __restrict__ W) {
    int i = blockIdx.x * blockDim.x + threadIdx.x;
    if (i < N_NODES) g_deg[i] = 0;
    if (i < 8 * 16 * 32) {
        int kt   = i >> 9;
        int ntp  = (i >> 5) & 15;
        int lane = i & 31;
        int g  = lane >> 2, tg = lane & 3;
        int ch0 = (ntp * 2) * 8 + g;
        int ch1 = (ntp * 2 + 1) * 8 + g;
        int k0  = kt * 16 + 2 * tg;
        const float* w0 = &W[(size_t)ch0 * IN_CH];
        const float* w1 = &W[(size_t)ch1 * IN_CH];
        uint4 v;
        v.x = h2u(__floats2half2_rn(w0[k0],     w0[k0 + 1]));
        v.y = h2u(__floats2half2_rn(w0[k0 + 8], w0[k0 + 9]));
        v.z = h2u(__floats2half2_rn(w1[k0],     w1[k0 + 1]));
        v.w = h2u(__floats2half2_rn(w1[k0 + 8], w1[k0 + 9]));
        g_WtPh[i] = v;
    }
}

// ------- K1: dst-degree histogram + per-edge rank ----------------
__global__ void k_hist(const int* __restrict__ ei) {
    int e = blockIdx.x * blockDim.x + threadIdx.x;
    if (e >= TOT_E) return;
    int d = (e < N_EDGES) ? ei[N_EDGES + e] : (e - N_EDGES);
    g_rank[e] = atomicAdd(&g_deg[d], 1);
}

// ---------------- K2: prefix scan stage A ----------------
__global__ void __launch_bounds__(1024) k_scanA() {
    __shared__ int s[1024];
    int i = blockIdx.x * 1024 + threadIdx.x;
    int v = (i < N_NODES) ? g_deg[i] : 0;
    s[threadIdx.x] = v;
    __syncthreads();
    #pragma unroll
    for (int off = 1; off < 1024; off <<= 1) {
        int u = (threadIdx.x >= off) ? s[threadIdx.x - off] : 0;
        __syncthreads();
        s[threadIdx.x] += u;
        __syncthreads();
    }
    if (i < N_NODES) g_incl[i] = s[threadIdx.x];
    if (threadIdx.x == 1023) g_bsum[blockIdx.x] = s[1023];
}

// ------- K3 (index 3): fp16 m16n8k16 GEMM + fused logits, fp16 store ----
__global__ void __launch_bounds__(256) k_gemm(const float* __restrict__ x,
                                              const float* __restrict__ att_src,
                                              const float* __restrict__ att_dst) {
    __shared__ __align__(16) __half xs[GB_TILE_M * XS_LDH];   // 8.7KB fp16
    const int n0    = blockIdx.x * GB_TILE_M;
    const int tid   = threadIdx.x;
    const int wid   = tid >> 5;
    const int lane  = tid & 31;
    const int g     = lane >> 2;
    const int tg    = lane & 3;
    const int mbase = (wid & 1) * 16;
    const int nq    = wid >> 1;           // n-quarter == head id (0..3)

    for (int i = tid; i < GB_TILE_M * 32; i += 256) {
        int node = i >> 5, col = i & 31;
        int gn = n0 + node; if (gn >= N_NODES) gn = N_NODES - 1;
        float4 v = ((const float4*)x)[(size_t)gn * 32 + col];
        uint2 h;
        h.x = h2u(__floats2half2_rn(v.x, v.y));
        h.y = h2u(__floats2half2_rn(v.z, v.w));
        *(uint2*)&xs[node * XS_LDH + col * 4] = h;
    }
    __syncthreads();

    float acc[8][4];
    #pragma unroll
    for (int t = 0; t < 8; t++)
        #pragma unroll
        for (int j = 0; j < 4; j++) acc[t][j] = 0.f;

    #pragma unroll
    for (int kt = 0; kt < 8; kt++) {
        const __half* r0 = &xs[(mbase + g)     * XS_LDH + kt * 16 + 2 * tg];
        const __half* r1 = &xs[(mbase + g + 8) * XS_LDH + kt * 16 + 2 * tg];
        unsigned a0 = *(const unsigned*)r0;
        unsigned a1 = *(const unsigned*)r1;
        unsigned a2 = *(const unsigned*)(r0 + 8);
        unsigned a3 = *(const unsigned*)(r1 + 8);
        #pragma unroll
        for (int j = 0; j < 4; j++) {
            uint4 b = g_WtPh[(size_t)(kt * 16 + nq * 4 + j) * 32 + lane];
            mma_f16(acc[2 * j],     a0, a1, a2, a3, b.x, b.y);
            mma_f16(acc[2 * j + 1], a0, a1, a2, a3, b.z, b.w);
        }
    }

    int node0 = n0 + mbase + g;
    int node1 = node0 + 8;
    float lps0 = 0.f, lps1 = 0.f, lpd0 = 0.f, lpd1 = 0.f;
    #pragma unroll
    for (int t = 0; t < 8; t++) {
        int ntile = nq * 8 + t;
        int ch = ntile * 8 + tg * 2;
        float2 av = *(const float2*)&att_src[ch];
        float2 dv = *(const float2*)&att_dst[ch];
        lps0 += acc[t][0] * av.x + acc[t][1] * av.y;
        lps1 += acc[t][2] * av.x + acc[t][3] * av.y;
        lpd0 += acc[t][0] * dv.x + acc[t][1] * dv.y;
        lpd1 += acc[t][2] * dv.x + acc[t][3] * dv.y;
        if (node0 < N_NODES)
            *(__half2*)&g_xh[(size_t)node0 * HC + ch] = __floats2half2_rn(acc[t][0], acc[t][1]);
        if (node1 < N_NODES)
            *(__half2*)&g_xh[(size_t)node1 * HC + ch] = __floats2half2_rn(acc[t][2], acc[t][3]);
    }
    #pragma unroll
    for (int off = 1; off <= 2; off <<= 1) {
        lps0 += __shfl_xor_sync(0xFFFFFFFFu, lps0, off);
        lps1 += __shfl_xor_sync(0xFFFFFFFFu, lps1, off);
        lpd0 += __shfl_xor_sync(0xFFFFFFFFu, lpd0, off);
        lpd1 += __shfl_xor_sync(0xFFFFFFFFu, lpd1, off);
    }
    if (tg == 0) {
        if (node0 < N_NODES) {
            g_asrc[(size_t)node0 * 4 + nq] = lps0;
            g_adst[(size_t)node0 * 4 + nq] = lpd0;
        }
        if (node1 < N_NODES) {
            g_asrc[(size_t)node1 * 4 + nq] = lps1;
            g_adst[(size_t)node1 * 4 + nq] = lpd1;
        }
    }
}

// ------- K4: scan stage C (inlines old scanB via per-block bsum prefix) --
__global__ void __launch_bounds__(1024) k_scanC() {
    __shared__ int boff_s;
    int i = blockIdx.x * 1024 + threadIdx.x;
    if (threadIdx.x < 32) {
        int v = 0;
        for (int b = threadIdx.x; b < blockIdx.x; b += 32) v += g_bsum[b];
        #pragma unroll
        for (int off = 16; off; off >>= 1) v += __shfl_xor_sync(0xFFFFFFFFu, v, off);
        if (threadIdx.x == 0) boff_s = v;
    }
    __syncthreads();
    if (i >= N_NODES) return;
    int incl = g_incl[i] + boff_s;
    g_ptr[i] = incl - g_deg[i];
    if (i == N_NODES - 1) g_ptr[N_NODES] = incl;
}

// ------- K5: fill sorted (src, exp) — no atomics -------
__global__ void k_fill(const int* __restrict__ ei) {
    int e = blockIdx.x * blockDim.x + threadIdx.x;
    if (e >= TOT_E) return;
    int s, d;
    if (e < N_EDGES) { s = ei[e]; d = ei[N_EDGES + e]; }
    else             { s = d = e - N_EDGES; }
    int pos = g_ptr[d] + g_rank[e];
    float4 as = *(const float4*)&g_asrc[(size_t)s * 4];
    float4 ad = *(const float4*)&g_adst[(size_t)d * 4];
    float4 ex;
    ex.x = expf(lrelu(as.x + ad.x));
    ex.y = expf(lrelu(as.y + ad.y));
    ex.z = expf(lrelu(as.z + ad.z));
    ex.w = expf(lrelu(as.w + ad.w));
    g_ssrc[pos] = s;
    *(float4*)&g_sexp[(size_t)pos * 4] = ex;
}

// ------- K6: fp16 gather-aggregate; lane owns 8 channels of one head ----
__global__ void __launch_bounds__(256) k_agg(const float* __restrict__ bias,
                                             float* __restrict__ out) {
    int w    = (blockIdx.x * blockDim.x + threadIdx.x) >> 5;   // node id
    int lane = threadIdx.x & 31;
    if (w >= N_NODES) return;
    const int p0 = g_ptr[w];
    const int p1 = g_ptr[w + 1];
    const int head = lane >> 3;           // 8 lanes per head

    float acc[8];
    #pragma unroll
    for (int j = 0; j < 8; j++) acc[j] = 0.f;
    float den = 0.f;

    int p = p0;
    for (; p + 8 <= p1; p += 8) {         // 8 gathers in flight
        int ss[8];
        #pragma unroll
        for (int j = 0; j < 8; j++) ss[j] = g_ssrc[p + j];
        uint4 rr[8];
        #pragma unroll
        for (int j = 0; j < 8; j++)
            rr[j] = ((const uint4*)&g_xh[(size_t)ss[j] * HC])[lane];
        float cc[8];
        #pragma unroll
        for (int j = 0; j < 8; j++)
            cc[j] = sel_head(*(const float4*)&g_sexp[(size_t)(p + j) * 4], head);
        #pragma unroll
        for (int j = 0; j < 8; j++) {
            den += cc[j];
            accum8(acc, rr[j], cc[j]);
        }
    }
    for (; p + 4 <= p1; p += 4) {
        int ss[4];
        #pragma unroll
        for (int j = 0; j < 4; j++) ss[j] = g_ssrc[p + j];
        uint4 rr[4];
        #pragma unroll
        for (int j = 0; j < 4; j++)
            rr[j] = ((const uint4*)&g_xh[(size_t)ss[j] * HC])[lane];
        #pragma unroll
        for (int j = 0; j < 4; j++) {
            float c = sel_head(*(const float4*)&g_sexp[(size_t)(p + j) * 4], head);
            den += c;
            accum8(acc, rr[j], c);
        }
    }
    for (; p < p1; p++) {
        int s = g_ssrc[p];
        uint4 r = ((const uint4*)&g_xh[(size_t)s * HC])[lane];
        float c = sel_head(*(const float4*)&g_sexp[(size_t)p * 4], head);
        den += c;
        accum8(acc, r, c);
    }

    float inv = 1.f / den;
    int ch0 = lane * 8;
    float4 b0 = *(const float4*)&bias[ch0];
    float4 b1 = *(const float4*)&bias[ch0 + 4];
    float4 o0, o1;
    o0.x = acc[0] * inv + b0.x; o0.y = acc[1] * inv + b0.y;
    o0.z = acc[2] * inv + b0.z; o0.w = acc[3] * inv + b0.w;
    o1.x = acc[4] * inv + b1.x; o1.y = acc[5] * inv + b1.y;
    o1.z = acc[6] * inv + b1.z; o1.w = acc[7] * inv + b1.w;
    o0.x = o0.x > 0.f ? o0.x : expm1f(o0.x);
    o0.y = o0.y > 0.f ? o0.y : expm1f(o0.y);
    o0.z = o0.z > 0.f ? o0.z : expm1f(o0.z);
    o0.w = o0.w > 0.f ? o0.w : expm1f(o0.w);
    o1.x = o1.x > 0.f ? o1.x : expm1f(o1.x);
    o1.y = o1.y > 0.f ? o1.y : expm1f(o1.y);
    o1.z = o1.z > 0.f ? o1.z : expm1f(o1.z);
    o1.w = o1.w > 0.f ? o1.w : expm1f(o1.w);
    *(float4*)&out[(size_t)w * HC + ch0]     = o0;
    *(float4*)&out[(size_t)w * HC + ch0 + 4] = o1;
}

extern "C" void kernel_launch(void* const* d_in, const int* in_sizes, int n_in,
                              void* d_out, int out_size) {
    const float* x    = (const float*)d_in[0];
    const int*   ei   = (const int*)d_in[1];    // int32 (JAX x64 disabled)
    const float* W    = (const float*)d_in[2];
    const float* asrc = (const float*)d_in[3];
    const float* adst = (const float*)d_in[4];
    const float* bias = (const float*)d_in[5];
    float* out = (float*)d_out;

    (void)in_sizes; (void)n_in; (void)out_size;

    // order keeps k_gemm at launch index 3 (the ncu-profiled slot)
    k_prep<<<(N_NODES + 255) / 256, 256>>>(W);
    k_hist<<<(TOT_E + 255) / 256, 256>>>(ei);
    k_scanA<<<SCAN_BLOCKS, 1024>>>();
    k_gemm<<<GB_BLOCKS, 256>>>(x, asrc, adst);
    k_scanC<<<SCAN_BLOCKS, 1024>>>();
    k_fill<<<(TOT_E + 255) / 256, 256>>>(ei);
    k_agg<<<(N_NODES * 32 + 255) / 256, 256>>>(bias, out);
}

// round 15
// speedup vs baseline: 1.0801x; 1.0801x over previous
#include <cuda_runtime.h>
#include <cuda_fp16.h>
#include <math.h>

#define N_NODES 50000
#define N_EDGES 800000
#define TOT_E   (N_EDGES + N_NODES)
#define IN_CH   128
#define HEADS   4
#define OUT_CH  64
#define HC      256
#define NEG_SLOPE 0.2f
#define SCAN_BLOCKS ((N_NODES + 1023) / 1024)   // 49
#define GB_TILE_M 32
#define GB_BLOCKS ((N_NODES + GB_TILE_M - 1) / GB_TILE_M)   // 1563
#define XS_LDH 136   // padded row stride in halves -> conflict-free frag loads

// ---- scratch (device globals; no allocation allowed) ----
__device__ __half g_xh [N_NODES * HC];      // projected features, fp16 (25.6MB, L2-resident)
__device__ float  g_asrc[N_NODES * HEADS];
__device__ float  g_adst[N_NODES * HEADS];
__device__ uint4  g_WtPh[8 * 16 * 32];      // B fragments fp16: [kt][ntp][lane]
__device__ int    g_deg [N_NODES];
__device__ int    g_rank[TOT_E];
__device__ int    g_incl[N_NODES];
__device__ int    g_bsum[SCAN_BLOCKS];
__device__ int    g_ptr [N_NODES + 1];      // CSR row ptr (by dst)
__device__ int    g_ssrc[TOT_E];            // dst-sorted: src node per slot
__device__ float  g_sexp[TOT_E * HEADS];    // dst-sorted: exp(alpha) per slot (fp32)

__device__ __forceinline__ float lrelu(float a) { return a > 0.f ? a : NEG_SLOPE * a; }

__device__ __forceinline__ unsigned h2u(__half2 h) {
    unsigned u; *(__half2*)&u = h; return u;
}
__device__ __forceinline__ void mma_f16(float* c,
                                        unsigned a0, unsigned a1, unsigned a2, unsigned a3,
                                        unsigned b0, unsigned b1) {
    asm("mma.sync.aligned.m16n8k16.row.col.f32.f16.f16.f32 "
        "{%0,%1,%2,%3}, {%4,%5,%6,%7}, {%8,%9}, {%0,%1,%2,%3};"
        : "+f"(c[0]), "+f"(c[1]), "+f"(c[2]), "+f"(c[3])
        : "r"(a0), "r"(a1), "r"(a2), "r"(a3), "r"(b0), "r"(b1));
}
__device__ __forceinline__ float sel_head(float4 e, int h) {
    return h == 0 ? e.x : (h == 1 ? e.y : (h == 2 ? e.z : e.w));
}
__device__ __forceinline__ void accum8(float* acc, uint4 r, float c) {
    const __half2* h = (const __half2*)&r;
    #pragma unroll
    for (int j = 0; j < 4; j++) {
        float2 f = __half22float2(h[j]);
        acc[2 * j]     += c * f.x;
        acc[2 * j + 1] += c * f.y;
    }
}

// ------- K0: zero deg + pack W into fp16 B-fragment layout -------
__global__ void k_prep(const float* __restrict__ W) {
    int i = blockIdx.x * blockDim.x + threadIdx.x;
    if (i < N_NODES) g_deg[i] = 0;
    if (i < 8 * 16 * 32) {
        int kt   = i >> 9;
        int ntp  = (i >> 5) & 15;
        int lane = i & 31;
        int g  = lane >> 2, tg = lane & 3;
        int ch0 = (ntp * 2) * 8 + g;
        int ch1 = (ntp * 2 + 1) * 8 + g;
        int k0  = kt * 16 + 2 * tg;
        const float* w0 = &W[(size_t)ch0 * IN_CH];
        const float* w1 = &W[(size_t)ch1 * IN_CH];
        uint4 v;
        v.x = h2u(__floats2half2_rn(w0[k0],     w0[k0 + 1]));
        v.y = h2u(__floats2half2_rn(w0[k0 + 8], w0[k0 + 9]));
        v.z = h2u(__floats2half2_rn(w1[k0],     w1[k0 + 1]));
        v.w = h2u(__floats2half2_rn(w1[k0 + 8], w1[k0 + 9]));
        g_WtPh[i] = v;
    }
}

// ------- K1: dst-degree histogram + per-edge rank ----------------
__global__ void k_hist(const int* __restrict__ ei) {
    int e = blockIdx.x * blockDim.x + threadIdx.x;
    if (e >= TOT_E) return;
    int d = (e < N_EDGES) ? ei[N_EDGES + e] : (e - N_EDGES);
    g_rank[e] = atomicAdd(&g_deg[d], 1);
}

// ---------------- K2: prefix scan stage A ----------------
__global__ void __launch_bounds__(1024) k_scanA() {
    __shared__ int s[1024];
    int i = blockIdx.x * 1024 + threadIdx.x;
    int v = (i < N_NODES) ? g_deg[i] : 0;
    s[threadIdx.x] = v;
    __syncthreads();
    #pragma unroll
    for (int off = 1; off < 1024; off <<= 1) {
        int u = (threadIdx.x >= off) ? s[threadIdx.x - off] : 0;
        __syncthreads();
        s[threadIdx.x] += u;
        __syncthreads();
    }
    if (i < N_NODES) g_incl[i] = s[threadIdx.x];
    if (threadIdx.x == 1023) g_bsum[blockIdx.x] = s[1023];
}

// ------- K3 (index 3): fp16 m16n8k16 GEMM + fused logits, fp16 store ----
__global__ void __launch_bounds__(256) k_gemm(const float* __restrict__ x,
                                              const float* __restrict__ att_src,
                                              const float* __restrict__ att_dst) {
    __shared__ __align__(16) __half xs[GB_TILE_M * XS_LDH];   // 8.7KB fp16
    const int n0    = blockIdx.x * GB_TILE_M;
    const int tid   = threadIdx.x;
    const int wid   = tid >> 5;
    const int lane  = tid & 31;
    const int g     = lane >> 2;
    const int tg    = lane & 3;
    const int mbase = (wid & 1) * 16;
    const int nq    = wid >> 1;           // n-quarter == head id (0..3)

    for (int i = tid; i < GB_TILE_M * 32; i += 256) {
        int node = i >> 5, col = i & 31;
        int gn = n0 + node; if (gn >= N_NODES) gn = N_NODES - 1;
        float4 v = ((const float4*)x)[(size_t)gn * 32 + col];
        uint2 h;
        h.x = h2u(__floats2half2_rn(v.x, v.y));
        h.y = h2u(__floats2half2_rn(v.z, v.w));
        *(uint2*)&xs[node * XS_LDH + col * 4] = h;
    }
    __syncthreads();

    float acc[8][4];
    #pragma unroll
    for (int t = 0; t < 8; t++)
        #pragma unroll
        for (int j = 0; j < 4; j++) acc[t][j] = 0.f;

    #pragma unroll
    for (int kt = 0; kt < 8; kt++) {
        const __half* r0 = &xs[(mbase + g)     * XS_LDH + kt * 16 + 2 * tg];
        const __half* r1 = &xs[(mbase + g + 8) * XS_LDH + kt * 16 + 2 * tg];
        unsigned a0 = *(const unsigned*)r0;
        unsigned a1 = *(const unsigned*)r1;
        unsigned a2 = *(const unsigned*)(r0 + 8);
        unsigned a3 = *(const unsigned*)(r1 + 8);
        #pragma unroll
        for (int j = 0; j < 4; j++) {
            uint4 b = g_WtPh[(size_t)(kt * 16 + nq * 4 + j) * 32 + lane];
            mma_f16(acc[2 * j],     a0, a1, a2, a3, b.x, b.y);
            mma_f16(acc[2 * j + 1], a0, a1, a2, a3, b.z, b.w);
        }
    }

    int node0 = n0 + mbase + g;
    int node1 = node0 + 8;
    float lps0 = 0.f, lps1 = 0.f, lpd0 = 0.f, lpd1 = 0.f;
    #pragma unroll
    for (int t = 0; t < 8; t++) {
        int ntile = nq * 8 + t;
        int ch = ntile * 8 + tg * 2;
        float2 av = *(const float2*)&att_src[ch];
        float2 dv = *(const float2*)&att_dst[ch];
        lps0 += acc[t][0] * av.x + acc[t][1] * av.y;
        lps1 += acc[t][2] * av.x + acc[t][3] * av.y;
        lpd0 += acc[t][0] * dv.x + acc[t][1] * dv.y;
        lpd1 += acc[t][2] * dv.x + acc[t][3] * dv.y;
        if (node0 < N_NODES)
            *(__half2*)&g_xh[(size_t)node0 * HC + ch] = __floats2half2_rn(acc[t][0], acc[t][1]);
        if (node1 < N_NODES)
            *(__half2*)&g_xh[(size_t)node1 * HC + ch] = __floats2half2_rn(acc[t][2], acc[t][3]);
    }
    #pragma unroll
    for (int off = 1; off <= 2; off <<= 1) {
        lps0 += __shfl_xor_sync(0xFFFFFFFFu, lps0, off);
        lps1 += __shfl_xor_sync(0xFFFFFFFFu, lps1, off);
        lpd0 += __shfl_xor_sync(0xFFFFFFFFu, lpd0, off);
        lpd1 += __shfl_xor_sync(0xFFFFFFFFu, lpd1, off);
    }
    if (tg == 0) {
        if (node0 < N_NODES) {
            g_asrc[(size_t)node0 * 4 + nq] = lps0;
            g_adst[(size_t)node0 * 4 + nq] = lpd0;
        }
        if (node1 < N_NODES) {
            g_asrc[(size_t)node1 * 4 + nq] = lps1;
            g_adst[(size_t)node1 * 4 + nq] = lpd1;
        }
    }
}

// ------- K4: scan stage C (inlines old scanB via per-block bsum prefix) --
__global__ void __launch_bounds__(1024) k_scanC() {
    __shared__ int boff_s;
    int i = blockIdx.x * 1024 + threadIdx.x;
    if (threadIdx.x < 32) {
        int v = 0;
        for (int b = threadIdx.x; b < blockIdx.x; b += 32) v += g_bsum[b];
        #pragma unroll
        for (int off = 16; off; off >>= 1) v += __shfl_xor_sync(0xFFFFFFFFu, v, off);
        if (threadIdx.x == 0) boff_s = v;
    }
    __syncthreads();
    if (i >= N_NODES) return;
    int incl = g_incl[i] + boff_s;
    g_ptr[i] = incl - g_deg[i];
    if (i == N_NODES - 1) g_ptr[N_NODES] = incl;
}

// ------- K5: fill sorted (src, exp) — no atomics -------
__global__ void k_fill(const int* __restrict__ ei) {
    int e = blockIdx.x * blockDim.x + threadIdx.x;
    if (e >= TOT_E) return;
    int s, d;
    if (e < N_EDGES) { s = ei[e]; d = ei[N_EDGES + e]; }
    else             { s = d = e - N_EDGES; }
    int pos = g_ptr[d] + g_rank[e];
    float4 as = *(const float4*)&g_asrc[(size_t)s * 4];
    float4 ad = *(const float4*)&g_adst[(size_t)d * 4];
    float4 ex;
    ex.x = expf(lrelu(as.x + ad.x));
    ex.y = expf(lrelu(as.y + ad.y));
    ex.z = expf(lrelu(as.z + ad.z));
    ex.w = expf(lrelu(as.w + ad.w));
    g_ssrc[pos] = s;
    *(float4*)&g_sexp[(size_t)pos * 4] = ex;
}

// ------- K6: fp16 gather-aggregate (R13-proven 4-way loop) --------------
__global__ void __launch_bounds__(256) k_agg(const float* __restrict__ bias,
                                             float* __restrict__ out) {
    int w    = (blockIdx.x * blockDim.x + threadIdx.x) >> 5;   // node id
    int lane = threadIdx.x & 31;
    if (w >= N_NODES) return;
    const int p0 = g_ptr[w];
    const int p1 = g_ptr[w + 1];
    const int head = lane >> 3;           // 8 lanes per head

    float acc[8];
    #pragma unroll
    for (int j = 0; j < 8; j++) acc[j] = 0.f;
    float den = 0.f;

    int p = p0;
    for (; p + 4 <= p1; p += 4) {         // 4 gathers in flight
        int s0 = g_ssrc[p];
        int s1 = g_ssrc[p + 1];
        int s2 = g_ssrc[p + 2];
        int s3 = g_ssrc[p + 3];
        uint4 r0 = ((const uint4*)&g_xh[(size_t)s0 * HC])[lane];
        uint4 r1 = ((const uint4*)&g_xh[(size_t)s1 * HC])[lane];
        uint4 r2 = ((const uint4*)&g_xh[(size_t)s2 * HC])[lane];
        uint4 r3 = ((const uint4*)&g_xh[(size_t)s3 * HC])[lane];
        float4 e0 = *(const float4*)&g_sexp[(size_t)p * 4];
        float4 e1 = *(const float4*)&g_sexp[(size_t)(p + 1) * 4];
        float4 e2 = *(const float4*)&g_sexp[(size_t)(p + 2) * 4];
        float4 e3 = *(const float4*)&g_sexp[(size_t)(p + 3) * 4];
        float c0 = sel_head(e0, head);
        float c1 = sel_head(e1, head);
        float c2 = sel_head(e2, head);
        float c3 = sel_head(e3, head);
        den += c0 + c1 + c2 + c3;
        accum8(acc, r0, c0);
        accum8(acc, r1, c1);
        accum8(acc, r2, c2);
        accum8(acc, r3, c3);
    }
    for (; p < p1; p++) {
        int s = g_ssrc[p];
        uint4 r = ((const uint4*)&g_xh[(size_t)s * HC])[lane];
        float c = sel_head(*(const float4*)&g_sexp[(size_t)p * 4], head);
        den += c;
        accum8(acc, r, c);
    }

    float inv = 1.f / den;
    int ch0 = lane * 8;
    float4 b0 = *(const float4*)&bias[ch0];
    float4 b1 = *(const float4*)&bias[ch0 + 4];
    float4 o0, o1;
    o0.x = acc[0] * inv + b0.x; o0.y = acc[1] * inv + b0.y;
    o0.z = acc[2] * inv + b0.z; o0.w = acc[3] * inv + b0.w;
    o1.x = acc[4] * inv + b1.x; o1.y = acc[5] * inv + b1.y;
    o1.z = acc[6] * inv + b1.z; o1.w = acc[7] * inv + b1.w;
    o0.x = o0.x > 0.f ? o0.x : expm1f(o0.x);
    o0.y = o0.y > 0.f ? o0.y : expm1f(o0.y);
    o0.z = o0.z > 0.f ? o0.z : expm1f(o0.z);
    o0.w = o0.w > 0.f ? o0.w : expm1f(o0.w);
    o1.x = o1.x > 0.f ? o1.x : expm1f(o1.x);
    o1.y = o1.y > 0.f ? o1.y : expm1f(o1.y);
    o1.z = o1.z > 0.f ? o1.z : expm1f(o1.z);
    o1.w = o1.w > 0.f ? o1.w : expm1f(o1.w);
    *(float4*)&out[(size_t)w * HC + ch0]     = o0;
    *(float4*)&out[(size_t)w * HC + ch0 + 4] = o1;
}

extern "C" void kernel_launch(void* const* d_in, const int* in_sizes, int n_in,
                              void* d_out, int out_size) {
    const float* x    = (const float*)d_in[0];
    const int*   ei   = (const int*)d_in[1];    // int32 (JAX x64 disabled)
    const float* W    = (const float*)d_in[2];
    const float* asrc = (const float*)d_in[3];
    const float* adst = (const float*)d_in[4];
    const float* bias = (const float*)d_in[5];
    float* out = (float*)d_out;

    (void)in_sizes; (void)n_in; (void)out_size;

    // order keeps k_gemm at launch index 3 (the ncu-profiled slot)
    k_prep<<<(N_NODES + 255) / 256, 256>>>(W);
    k_hist<<<(TOT_E + 255) / 256, 256>>>(ei);
    k_scanA<<<SCAN_BLOCKS, 1024>>>();
    k_gemm<<<GB_BLOCKS, 256>>>(x, asrc, adst);
    k_scanC<<<SCAN_BLOCKS, 1024>>>();
    k_fill<<<(TOT_E + 255) / 256, 256>>>(ei);
    k_agg<<<(N_NODES * 32 + 255) / 256, 256>>>(bias, out);
}

// round 16
// speedup vs baseline: 1.1669x; 1.0803x over previous
#include <cuda_runtime.h>
#include <cuda_fp16.h>
#include <math.h>

#define N_NODES 50000
#define N_EDGES 800000
#define TOT_E   (N_EDGES + N_NODES)
#define IN_CH   128
#define HEADS   4
#define OUT_CH  64
#define HC      256
#define NEG_SLOPE 0.2f
#define SCAN_BLOCKS ((N_NODES + 1023) / 1024)   // 49
#define GB_TILE_M 32
#define GB_BLOCKS ((N_NODES + GB_TILE_M - 1) / GB_TILE_M)   // 1563
#define XS_LDH 136   // padded row stride in halves -> conflict-free frag loads

// ---- scratch (device globals; no allocation allowed) ----
__device__ __half g_xh [N_NODES * HC];      // projected features, fp16 (25.6MB, L2-resident)
__device__ float  g_asrc[N_NODES * HEADS];
__device__ float  g_adst[N_NODES * HEADS];
__device__ uint4  g_WtPh[8 * 16 * 32];      // B fragments fp16: [kt][ntp][lane]
__device__ int    g_deg [N_NODES];
__device__ int    g_rank[TOT_E];
__device__ int    g_incl[N_NODES];
__device__ int    g_bsum[SCAN_BLOCKS];
__device__ int    g_ptr [N_NODES + 1];      // CSR row ptr (by dst)
__device__ int    g_ssrc[TOT_E];            // dst-sorted: src node per slot
__device__ float  g_sexp[TOT_E * HEADS];    // dst-sorted: exp(alpha) per slot (fp32)

__device__ __forceinline__ float lrelu(float a) { return a > 0.f ? a : NEG_SLOPE * a; }

__device__ __forceinline__ unsigned h2u(__half2 h) {
    unsigned u; *(__half2*)&u = h; return u;
}
__device__ __forceinline__ void mma_f16(float* c,
                                        unsigned a0, unsigned a1, unsigned a2, unsigned a3,
                                        unsigned b0, unsigned b1) {
    asm("mma.sync.aligned.m16n8k16.row.col.f32.f16.f16.f32 "
        "{%0,%1,%2,%3}, {%4,%5,%6,%7}, {%8,%9}, {%0,%1,%2,%3};"
        : "+f"(c[0]), "+f"(c[1]), "+f"(c[2]), "+f"(c[3])
        : "r"(a0), "r"(a1), "r"(a2), "r"(a3), "r"(b0), "r"(b1));
}
__device__ __forceinline__ float sel_head(float4 e, int h) {
    return h == 0 ? e.x : (h == 1 ? e.y : (h == 2 ? e.z : e.w));
}
__device__ __forceinline__ void accum8(float* acc, uint4 r, float c) {
    const __half2* h = (const __half2*)&r;
    #pragma unroll
    for (int j = 0; j < 4; j++) {
        float2 f = __half22float2(h[j]);
        acc[2 * j]     += c * f.x;
        acc[2 * j + 1] += c * f.y;
    }
}

// ------- K0: zero deg + pack W into fp16 B-fragment layout -------
__global__ void k_prep(const float* __restrict__ W) {
    int i = blockIdx.x * blockDim.x + threadIdx.x;
    if (i < N_NODES) g_deg[i] = 0;
    if (i < 8 * 16 * 32) {
        int kt   = i >> 9;
        int ntp  = (i >> 5) & 15;
        int lane = i & 31;
        int g  = lane >> 2, tg = lane & 3;
        int ch0 = (ntp * 2) * 8 + g;
        int ch1 = (ntp * 2 + 1) * 8 + g;
        int k0  = kt * 16 + 2 * tg;
        const float* w0 = &W[(size_t)ch0 * IN_CH];
        const float* w1 = &W[(size_t)ch1 * IN_CH];
        uint4 v;
        v.x = h2u(__floats2half2_rn(w0[k0],     w0[k0 + 1]));
        v.y = h2u(__floats2half2_rn(w0[k0 + 8], w0[k0 + 9]));
        v.z = h2u(__floats2half2_rn(w1[k0],     w1[k0 + 1]));
        v.w = h2u(__floats2half2_rn(w1[k0 + 8], w1[k0 + 9]));
        g_WtPh[i] = v;
    }
}

// ------- K1 (side stream): dst-degree histogram + per-edge rank ---------
__global__ void k_hist(const int* __restrict__ ei) {
    int e = blockIdx.x * blockDim.x + threadIdx.x;
    if (e >= TOT_E) return;
    int d = (e < N_EDGES) ? ei[N_EDGES + e] : (e - N_EDGES);
    g_rank[e] = atomicAdd(&g_deg[d], 1);
}

// ---------------- K2 (side stream): prefix scan stage A ----------------
__global__ void __launch_bounds__(1024) k_scanA() {
    __shared__ int s[1024];
    int i = blockIdx.x * 1024 + threadIdx.x;
    int v = (i < N_NODES) ? g_deg[i] : 0;
    s[threadIdx.x] = v;
    __syncthreads();
    #pragma unroll
    for (int off = 1; off < 1024; off <<= 1) {
        int u = (threadIdx.x >= off) ? s[threadIdx.x - off] : 0;
        __syncthreads();
        s[threadIdx.x] += u;
        __syncthreads();
    }
    if (i < N_NODES) g_incl[i] = s[threadIdx.x];
    if (threadIdx.x == 1023) g_bsum[blockIdx.x] = s[1023];
}

// ------- K3 (side stream): scan stage C (inlined scanB prefix) ----------
__global__ void __launch_bounds__(1024) k_scanC() {
    __shared__ int boff_s;
    int i = blockIdx.x * 1024 + threadIdx.x;
    if (threadIdx.x < 32) {
        int v = 0;
        for (int b = threadIdx.x; b < blockIdx.x; b += 32) v += g_bsum[b];
        #pragma unroll
        for (int off = 16; off; off >>= 1) v += __shfl_xor_sync(0xFFFFFFFFu, v, off);
        if (threadIdx.x == 0) boff_s = v;
    }
    __syncthreads();
    if (i >= N_NODES) return;
    int incl = g_incl[i] + boff_s;
    g_ptr[i] = incl - g_deg[i];
    if (i == N_NODES - 1) g_ptr[N_NODES] = incl;
}

// ------- K4 (main, overlapped with side): fp16 MMA GEMM + fused logits --
__global__ void __launch_bounds__(256) k_gemm(const float* __restrict__ x,
                                              const float* __restrict__ att_src,
                                              const float* __restrict__ att_dst) {
    __shared__ __align__(16) __half xs[GB_TILE_M * XS_LDH];   // 8.7KB fp16
    const int n0    = blockIdx.x * GB_TILE_M;
    const int tid   = threadIdx.x;
    const int wid   = tid >> 5;
    const int lane  = tid & 31;
    const int g     = lane >> 2;
    const int tg    = lane & 3;
    const int mbase = (wid & 1) * 16;
    const int nq    = wid >> 1;           // n-quarter == head id (0..3)

    for (int i = tid; i < GB_TILE_M * 32; i += 256) {
        int node = i >> 5, col = i & 31;
        int gn = n0 + node; if (gn >= N_NODES) gn = N_NODES - 1;
        float4 v = ((const float4*)x)[(size_t)gn * 32 + col];
        uint2 h;
        h.x = h2u(__floats2half2_rn(v.x, v.y));
        h.y = h2u(__floats2half2_rn(v.z, v.w));
        *(uint2*)&xs[node * XS_LDH + col * 4] = h;
    }
    __syncthreads();

    float acc[8][4];
    #pragma unroll
    for (int t = 0; t < 8; t++)
        #pragma unroll
        for (int j = 0; j < 4; j++) acc[t][j] = 0.f;

    #pragma unroll
    for (int kt = 0; kt < 8; kt++) {
        const __half* r0 = &xs[(mbase + g)     * XS_LDH + kt * 16 + 2 * tg];
        const __half* r1 = &xs[(mbase + g + 8) * XS_LDH + kt * 16 + 2 * tg];
        unsigned a0 = *(const unsigned*)r0;
        unsigned a1 = *(const unsigned*)r1;
        unsigned a2 = *(const unsigned*)(r0 + 8);
        unsigned a3 = *(const unsigned*)(r1 + 8);
        #pragma unroll
        for (int j = 0; j < 4; j++) {
            uint4 b = g_WtPh[(size_t)(kt * 16 + nq * 4 + j) * 32 + lane];
            mma_f16(acc[2 * j],     a0, a1, a2, a3, b.x, b.y);
            mma_f16(acc[2 * j + 1], a0, a1, a2, a3, b.z, b.w);
        }
    }

    int node0 = n0 + mbase + g;
    int node1 = node0 + 8;
    float lps0 = 0.f, lps1 = 0.f, lpd0 = 0.f, lpd1 = 0.f;
    #pragma unroll
    for (int t = 0; t < 8; t++) {
        int ntile = nq * 8 + t;
        int ch = ntile * 8 + tg * 2;
        float2 av = *(const float2*)&att_src[ch];
        float2 dv = *(const float2*)&att_dst[ch];
        lps0 += acc[t][0] * av.x + acc[t][1] * av.y;
        lps1 += acc[t][2] * av.x + acc[t][3] * av.y;
        lpd0 += acc[t][0] * dv.x + acc[t][1] * dv.y;
        lpd1 += acc[t][2] * dv.x + acc[t][3] * dv.y;
        if (node0 < N_NODES)
            *(__half2*)&g_xh[(size_t)node0 * HC + ch] = __floats2half2_rn(acc[t][0], acc[t][1]);
        if (node1 < N_NODES)
            *(__half2*)&g_xh[(size_t)node1 * HC + ch] = __floats2half2_rn(acc[t][2], acc[t][3]);
    }
    #pragma unroll
    for (int off = 1; off <= 2; off <<= 1) {
        lps0 += __shfl_xor_sync(0xFFFFFFFFu, lps0, off);
        lps1 += __shfl_xor_sync(0xFFFFFFFFu, lps1, off);
        lpd0 += __shfl_xor_sync(0xFFFFFFFFu, lpd0, off);
        lpd1 += __shfl_xor_sync(0xFFFFFFFFu, lpd1, off);
    }
    if (tg == 0) {
        if (node0 < N_NODES) {
            g_asrc[(size_t)node0 * 4 + nq] = lps0;
            g_adst[(size_t)node0 * 4 + nq] = lpd0;
        }
        if (node1 < N_NODES) {
            g_asrc[(size_t)node1 * 4 + nq] = lps1;
            g_adst[(size_t)node1 * 4 + nq] = lpd1;
        }
    }
}

// ------- K5: fill sorted (src, exp) — no atomics -------
__global__ void k_fill(const int* __restrict__ ei) {
    int e = blockIdx.x * blockDim.x + threadIdx.x;
    if (e >= TOT_E) return;
    int s, d;
    if (e < N_EDGES) { s = ei[e]; d = ei[N_EDGES + e]; }
    else             { s = d = e - N_EDGES; }
    int pos = g_ptr[d] + g_rank[e];
    float4 as = *(const float4*)&g_asrc[(size_t)s * 4];
    float4 ad = *(const float4*)&g_adst[(size_t)d * 4];
    float4 ex;
    ex.x = expf(lrelu(as.x + ad.x));
    ex.y = expf(lrelu(as.y + ad.y));
    ex.z = expf(lrelu(as.z + ad.z));
    ex.w = expf(lrelu(as.w + ad.w));
    g_ssrc[pos] = s;
    *(float4*)&g_sexp[(size_t)pos * 4] = ex;
}

// ------- K6: fp16 gather-aggregate (R13-proven 4-way loop) --------------
__global__ void __launch_bounds__(256) k_agg(const float* __restrict__ bias,
                                             float* __restrict__ out) {
    int w    = (blockIdx.x * blockDim.x + threadIdx.x) >> 5;   // node id
    int lane = threadIdx.x & 31;
    if (w >= N_NODES) return;
    const int p0 = g_ptr[w];
    const int p1 = g_ptr[w + 1];
    const int head = lane >> 3;           // 8 lanes per head

    float acc[8];
    #pragma unroll
    for (int j = 0; j < 8; j++) acc[j] = 0.f;
    float den = 0.f;

    int p = p0;
    for (; p + 4 <= p1; p += 4) {         // 4 gathers in flight
        int s0 = g_ssrc[p];
        int s1 = g_ssrc[p + 1];
        int s2 = g_ssrc[p + 2];
        int s3 = g_ssrc[p + 3];
        uint4 r0 = ((const uint4*)&g_xh[(size_t)s0 * HC])[lane];
        uint4 r1 = ((const uint4*)&g_xh[(size_t)s1 * HC])[lane];
        uint4 r2 = ((const uint4*)&g_xh[(size_t)s2 * HC])[lane];
        uint4 r3 = ((const uint4*)&g_xh[(size_t)s3 * HC])[lane];
        float4 e0 = *(const float4*)&g_sexp[(size_t)p * 4];
        float4 e1 = *(const float4*)&g_sexp[(size_t)(p + 1) * 4];
        float4 e2 = *(const float4*)&g_sexp[(size_t)(p + 2) * 4];
        float4 e3 = *(const float4*)&g_sexp[(size_t)(p + 3) * 4];
        float c0 = sel_head(e0, head);
        float c1 = sel_head(e1, head);
        float c2 = sel_head(e2, head);
        float c3 = sel_head(e3, head);
        den += c0 + c1 + c2 + c3;
        accum8(acc, r0, c0);
        accum8(acc, r1, c1);
        accum8(acc, r2, c2);
        accum8(acc, r3, c3);
    }
    for (; p < p1; p++) {
        int s = g_ssrc[p];
        uint4 r = ((const uint4*)&g_xh[(size_t)s * HC])[lane];
        float c = sel_head(*(const float4*)&g_sexp[(size_t)p * 4], head);
        den += c;
        accum8(acc, r, c);
    }

    float inv = 1.f / den;
    int ch0 = lane * 8;
    float4 b0 = *(const float4*)&bias[ch0];
    float4 b1 = *(const float4*)&bias[ch0 + 4];
    float4 o0, o1;
    o0.x = acc[0] * inv + b0.x; o0.y = acc[1] * inv + b0.y;
    o0.z = acc[2] * inv + b0.z; o0.w = acc[3] * inv + b0.w;
    o1.x = acc[4] * inv + b1.x; o1.y = acc[5] * inv + b1.y;
    o1.z = acc[6] * inv + b1.z; o1.w = acc[7] * inv + b1.w;
    o0.x = o0.x > 0.f ? o0.x : expm1f(o0.x);
    o0.y = o0.y > 0.f ? o0.y : expm1f(o0.y);
    o0.z = o0.z > 0.f ? o0.z : expm1f(o0.z);
    o0.w = o0.w > 0.f ? o0.w : expm1f(o0.w);
    o1.x = o1.x > 0.f ? o1.x : expm1f(o1.x);
    o1.y = o1.y > 0.f ? o1.y : expm1f(o1.y);
    o1.z = o1.z > 0.f ? o1.z : expm1f(o1.z);
    o1.w = o1.w > 0.f ? o1.w : expm1f(o1.w);
    *(float4*)&out[(size_t)w * HC + ch0]     = o0;
    *(float4*)&out[(size_t)w * HC + ch0 + 4] = o1;
}

extern "C" void kernel_launch(void* const* d_in, const int* in_sizes, int n_in,
                              void* d_out, int out_size) {
    const float* x    = (const float*)d_in[0];
    const int*   ei   = (const int*)d_in[1];    // int32 (JAX x64 disabled)
    const float* W    = (const float*)d_in[2];
    const float* asrc = (const float*)d_in[3];
    const float* adst = (const float*)d_in[4];
    const float* bias = (const float*)d_in[5];
    float* out = (float*)d_out;

    (void)in_sizes; (void)n_in; (void)out_size;

    // One-time driver-resource setup (no device memory; created on the
    // non-captured correctness call, reused identically thereafter).
    static cudaStream_t s_side = nullptr;
    static cudaEvent_t  s_evA  = nullptr;   // prep done -> side may start
    static cudaEvent_t  s_evB  = nullptr;   // side chain done -> main may fill
    if (!s_side) {
        cudaStreamCreateWithFlags(&s_side, cudaStreamNonBlocking);
        cudaEventCreateWithFlags(&s_evA, cudaEventDisableTiming);
        cudaEventCreateWithFlags(&s_evB, cudaEventDisableTiming);
    }

    // main: prep (zero deg + pack W)
    k_prep<<<(N_NODES + 255) / 256, 256>>>(W);
    cudaEventRecord(s_evA, 0);

    // side branch: graph build (hist -> scanA -> scanC), overlapped with gemm
    cudaStreamWaitEvent(s_side, s_evA, 0);
    k_hist<<<(TOT_E + 255) / 256, 256, 0, s_side>>>(ei);
    k_scanA<<<SCAN_BLOCKS, 1024, 0, s_side>>>();
    k_scanC<<<SCAN_BLOCKS, 1024, 0, s_side>>>();
    cudaEventRecord(s_evB, s_side);

    // main branch: GEMM (independent of side), then join
    k_gemm<<<GB_BLOCKS, 256>>>(x, asrc, adst);
    cudaStreamWaitEvent(0, s_evB, 0);

    // joined: fill + aggregate
    k_fill<<<(TOT_E + 255) / 256, 256>>>(ei);
    k_agg<<<(N_NODES * 32 + 255) / 256, 256>>>(bias, out);
}